// round 15
// baseline (speedup 1.0000x reference)
#include <cuda_runtime.h>
#include <cuda_bf16.h>
#include <cstdint>

// HashGridEncoding R15 == R14 resubmitted verbatim (R14 bench failed on
// "device busy" infra error before any launch; hypothesis untested).
// R13 skeleton (level-paired half-warps, staged x + staged coalesced output)
// scaled to 64 points / 576-thread block to halve per-point barrier + ramp
// overhead. sres laid out [level][point(+pad)] so gather-phase STS.64 is
// bank-conflict-free; write-out = exactly 1 float2/thread.
//
// Warp k in 0..8  -> points 0..31,  lanes 0-15 level k, lanes 16-31 level 8-k.
// Warp k in 9..17 -> points 32..63, same level mapping (perfect balance).

#define NUM_LEVELS 9
#define PTS 64                 // points per block
#define SPAD 2                 // pad sres rows to 66 float2 (bank-friendly)

__device__ __forceinline__ void load_pair(const float4* __restrict__ t4, int b,
                                          float2& q0, float2& q1)
{
    int a = b >> 1;
    float4 qa = __ldg(t4 + a);
    if (b & 1) {
        float4 qb = __ldg(t4 + a + 1);       // predicated: odd-b lanes only
        q0 = make_float2(qa.z, qa.w);
        q1 = make_float2(qb.x, qb.y);
    } else {
        q0 = make_float2(qa.x, qa.y);
        q1 = make_float2(qa.z, qa.w);
    }
}

__global__ void __launch_bounds__(576) hashgrid_kernel(
    const float* __restrict__ x,
    const float* __restrict__ table,
    float* __restrict__ out,
    int P)
{
    __shared__ float  sx[PTS * 3];                       // 64 pts x 3
    __shared__ float2 sres[NUM_LEVELS][PTS + SPAD];      // [level][point]

    int pbase = blockIdx.x * PTS;
    int t = threadIdx.x;

    if (t < PTS * 3) {
        int g = pbase * 3 + t;
        sx[t] = (g < P * 3) ? x[g] : 0.0f;
    }
    __syncthreads();

    int wid  = t >> 5;                  // 0..17
    int lane = t & 31;
    int k    = (wid >= NUM_LEVELS) ? wid - NUM_LEVELS : wid;   // 0..8
    int half = (wid >= NUM_LEVELS) ? 32 : 0;

    // level-paired mapping within each 9-warp group
    int lvl = (lane < 16) ? k : (8 - k);
    int pt  = half + lane;

    {
        int   vi = 1 << lvl;
        float vf = (float)vi;

        float gx = (sx[pt * 3 + 0] + 1.0f) * 0.5f * vf;
        float gy = (sx[pt * 3 + 1] + 1.0f) * 0.5f * vf;
        float gz = (sx[pt * 3 + 2] + 1.0f) * 0.5f * vf;

        float bxf = floorf(gx), byf = floorf(gy), bzf = floorf(gz);
        float fx = gx - bxf, fy = gy - byf, fz = gz - bzf;

        int ix = (int)bxf, iy = (int)byf, iz = (int)bzf;
        int flat = ix + iy * vi + iz * vi * vi;
        int dz   = vi * vi;

        const float4* __restrict__ tab4 = (const float4*)table;

        float2 q000, q100, q010, q110, q001, q101, q011, q111;
        load_pair(tab4, flat,           q000, q100);
        load_pair(tab4, flat + vi,      q010, q110);
        load_pair(tab4, flat + dz,      q001, q101);
        load_pair(tab4, flat + dz + vi, q011, q111);

        float wx0 = 1.0f - fx, wx1 = fx;
        float wy0 = 1.0f - fy, wy1 = fy;
        float wz0 = 1.0f - fz, wz1 = fz;

        float a0x = wx0 * q000.x + wx1 * q100.x;
        float a0y = wx0 * q000.y + wx1 * q100.y;
        float a1x = wx0 * q010.x + wx1 * q110.x;
        float a1y = wx0 * q010.y + wx1 * q110.y;
        float a2x = wx0 * q001.x + wx1 * q101.x;
        float a2y = wx0 * q001.y + wx1 * q101.y;
        float a3x = wx0 * q011.x + wx1 * q111.x;
        float a3y = wx0 * q011.y + wx1 * q111.y;

        float b0x = wy0 * a0x + wy1 * a1x;
        float b0y = wy0 * a0y + wy1 * a1y;
        float b1x = wy0 * a2x + wy1 * a3x;
        float b1y = wy0 * a2y + wy1 * a3y;

        sres[lvl][pt] = make_float2(wz0 * b0x + wz1 * b1x,
                                    wz0 * b0y + wz1 * b1y);
    }
    __syncthreads();

    // write-out: 576 float2 = 64 points x 9 levels, 1 per thread, coalesced
    int pi = t / NUM_LEVELS;
    int li = t - pi * NUM_LEVELS;
    int p  = pbase + pi;
    if (p < P) {
        float2* __restrict__ o2 = (float2*)out;
        o2[p * NUM_LEVELS + li] = sres[li][pi];
    }
}

extern "C" void kernel_launch(void* const* d_in, const int* in_sizes, int n_in,
                              void* d_out, int out_size)
{
    const float* x     = (const float*)d_in[0];
    const float* table = (const float*)d_in[1];
    float* out         = (float*)d_out;

    int P = in_sizes[0] / 3;
    int blocks = (P + PTS - 1) / PTS;   // 64 points per block, 18 warps
    hashgrid_kernel<<<blocks, 576>>>(x, table, out, P);
}

// round 16
// speedup vs baseline: 1.0608x; 1.0608x over previous
#include <cuda_runtime.h>
#include <cuda_bf16.h>
#include <cstdint>

// HashGridEncoding R16: R13 skeleton (288 thr / 32 pts, level-paired
// half-warps, staged x + coalesced staged output) + SMEM CACHE of
// table[0..585) serving ALL gathers for levels 0..3.
// Key fact: flat = ix + iy*vi + iz*vi^2 has NO level offset, so l0..l3
// corner indices all lie in table[0..585) (max l3 corner = 511+73 = 584).
// Each block re-reads that 4.7KB region ~250 wavefronts' worth via LDG;
// caching costs ~74 wavefronts once and LDS gathers are ~3x cheaper.

#define NUM_LEVELS 9
#define LOWTAB 585          // entries 0..584 cover all l0..l3 corners

__device__ __forceinline__ void load_pair(const float4* __restrict__ t4, int b,
                                          float2& q0, float2& q1)
{
    int a = b >> 1;
    float4 qa = __ldg(t4 + a);
    if (b & 1) {
        float4 qb = __ldg(t4 + a + 1);       // predicated: odd-b lanes only
        q0 = make_float2(qa.z, qa.w);
        q1 = make_float2(qb.x, qb.y);
    } else {
        q0 = make_float2(qa.x, qa.y);
        q1 = make_float2(qa.z, qa.w);
    }
}

__global__ void __launch_bounds__(288) hashgrid_kernel(
    const float* __restrict__ x,
    const float* __restrict__ table,
    float* __restrict__ out,
    int P)
{
    __shared__ float  sx[96];                  // 32 points x 3 coords
    __shared__ float2 st[LOWTAB];              // table[0..585) cache
    __shared__ float2 sres[32][NUM_LEVELS];

    int pbase = blockIdx.x * 32;
    int t = threadIdx.x;

    if (t < 96) {
        int g = pbase * 3 + t;
        sx[t] = (g < P * 3) ? x[g] : 0.0f;
    }
    // preload low-table: 585 float2 by 288 threads (coalesced, L1/L2-hot)
    const float2* __restrict__ tab2 = (const float2*)table;
    for (int e = t; e < LOWTAB; e += 288) st[e] = __ldg(tab2 + e);
    __syncthreads();

    int k    = t >> 5;                  // warp id (0..8)
    int lane = t & 31;

    // level-paired mapping: lanes 0-15 -> level k, lanes 16-31 -> level 8-k
    int lvl = (lane < 16) ? k : (8 - k);
    int pt  = lane;

    {
        int   vi = 1 << lvl;
        float vf = (float)vi;

        float gx = (sx[pt * 3 + 0] + 1.0f) * 0.5f * vf;
        float gy = (sx[pt * 3 + 1] + 1.0f) * 0.5f * vf;
        float gz = (sx[pt * 3 + 2] + 1.0f) * 0.5f * vf;

        float bxf = floorf(gx), byf = floorf(gy), bzf = floorf(gz);
        float fx = gx - bxf, fy = gy - byf, fz = gz - bzf;

        int ix = (int)bxf, iy = (int)byf, iz = (int)bzf;
        int flat = ix + iy * vi + iz * vi * vi;
        int dz   = vi * vi;

        float2 q000, q100, q010, q110, q001, q101, q011, q111;
        if (lvl <= 3) {
            // all 8 corner indices < 585: gather from smem
            q000 = st[flat];
            q100 = st[flat + 1];
            q010 = st[flat + vi];
            q110 = st[flat + vi + 1];
            q001 = st[flat + dz];
            q101 = st[flat + dz + 1];
            q011 = st[flat + dz + vi];
            q111 = st[flat + dz + vi + 1];
        } else {
            const float4* __restrict__ tab4 = (const float4*)table;
            load_pair(tab4, flat,           q000, q100);
            load_pair(tab4, flat + vi,      q010, q110);
            load_pair(tab4, flat + dz,      q001, q101);
            load_pair(tab4, flat + dz + vi, q011, q111);
        }

        float wx0 = 1.0f - fx, wx1 = fx;
        float wy0 = 1.0f - fy, wy1 = fy;
        float wz0 = 1.0f - fz, wz1 = fz;

        float a0x = wx0 * q000.x + wx1 * q100.x;
        float a0y = wx0 * q000.y + wx1 * q100.y;
        float a1x = wx0 * q010.x + wx1 * q110.x;
        float a1y = wx0 * q010.y + wx1 * q110.y;
        float a2x = wx0 * q001.x + wx1 * q101.x;
        float a2y = wx0 * q001.y + wx1 * q101.y;
        float a3x = wx0 * q011.x + wx1 * q111.x;
        float a3y = wx0 * q011.y + wx1 * q111.y;

        float b0x = wy0 * a0x + wy1 * a1x;
        float b0y = wy0 * a0y + wy1 * a1y;
        float b1x = wy0 * a2x + wy1 * a3x;
        float b1y = wy0 * a2y + wy1 * a3y;

        sres[pt][lvl] = make_float2(wz0 * b0x + wz1 * b1x,
                                    wz0 * b0y + wz1 * b1y);
    }
    __syncthreads();

    // write-out: 288 float2 = 32 points x 9 levels, fully coalesced 2304B
    int pi = t / NUM_LEVELS;
    int li = t - pi * NUM_LEVELS;
    int p  = pbase + pi;
    if (p < P) {
        float2* __restrict__ o2 = (float2*)out;
        o2[p * NUM_LEVELS + li] = sres[pi][li];
    }
}

extern "C" void kernel_launch(void* const* d_in, const int* in_sizes, int n_in,
                              void* d_out, int out_size)
{
    const float* x     = (const float*)d_in[0];
    const float* table = (const float*)d_in[1];
    float* out         = (float*)d_out;

    int P = in_sizes[0] / 3;
    int blocks = (P + 31) / 32;        // 32 points per block, 9 warps
    hashgrid_kernel<<<blocks, 288>>>(x, table, out, P);
}